// round 3
// baseline (speedup 1.0000x reference)
#include <cuda_runtime.h>

// Erosion2d: 3x3 windowed min, stride 1, pad value 1e9, over (16,64,256,256) fp32.
// Memory-bound streaming kernel: separable horizontal 3-min + register-rolled
// vertical 3-min. Each thread produces a 4-wide (float4) x T-tall output strip.

#define PAD_VALF 1e9f

constexpr int H = 256;
constexpr int W = 256;
constexpr int W4 = W / 4;   // 64 float4 lanes per row
constexpr int T  = 8;       // rows per thread (read amplification (T+2)/T = 1.25)

__device__ __forceinline__ float4 fmin4(float4 a, float4 b) {
    float4 r;
    r.x = fminf(a.x, b.x);
    r.y = fminf(a.y, b.y);
    r.z = fminf(a.z, b.z);
    r.w = fminf(a.w, b.w);
    return r;
}

__global__ __launch_bounds__(256) void erosion3x3_kernel(
    const float* __restrict__ in, float* __restrict__ out)
{
    const int x4 = threadIdx.x;                                   // 0..63
    const int xb = x4 * 4;
    const int y0 = (blockIdx.y * blockDim.y + threadIdx.y) * T;   // strip top
    const long long plane = blockIdx.z;                           // n*c plane

    const float* __restrict__ p = in  + plane * (long long)(H * W);
    float*       __restrict__ q = out + plane * (long long)(H * W);

    const bool left_edge  = (x4 == 0);
    const bool right_edge = (x4 == W4 - 1);

    // Horizontal 3-min of row y for this thread's 4 output columns.
    auto hmin_row = [&](int y) -> float4 {
        const float* row = p + y * W + xb;
        float4 v = *reinterpret_cast<const float4*>(row);
        float l = left_edge  ? PAD_VALF : __ldg(row - 1);
        float r = right_edge ? PAD_VALF : __ldg(row + 4);
        float4 h;
        h.x = fminf(l,   fminf(v.x, v.y));
        h.y = fminf(v.x, fminf(v.y, v.z));
        h.z = fminf(v.y, fminf(v.z, v.w));
        h.w = fminf(v.z, fminf(v.w, r));
        return h;
    };

    const float4 padv = make_float4(PAD_VALF, PAD_VALF, PAD_VALF, PAD_VALF);

    // Rolling 3-row window of horizontal mins: a = y-1, b = y, c = y+1.
    float4 a = (y0 > 0) ? hmin_row(y0 - 1) : padv;
    float4 b = hmin_row(y0);

    #pragma unroll
    for (int i = 0; i < T; i++) {
        const int y = y0 + i;
        float4 c = (y + 1 < H) ? hmin_row(y + 1) : padv;
        float4 o = fmin4(a, fmin4(b, c));
        *reinterpret_cast<float4*>(q + y * W + xb) = o;
        a = b;
        b = c;
    }
}

extern "C" void kernel_launch(void* const* d_in, const int* in_sizes, int n_in,
                              void* d_out, int out_size)
{
    const float* x = (const float*)d_in[0];
    float* out = (float*)d_out;

    const int planes = in_sizes[0] / (H * W);   // 16 * 64 = 1024

    dim3 block(W4, 4, 1);                 // 64 x 4 = 256 threads
    dim3 grid(1, H / (4 * T), planes);    // (1, 8, 1024)
    erosion3x3_kernel<<<grid, block>>>(x, out);
}